// round 2
// baseline (speedup 1.0000x reference)
#include <cuda_runtime.h>

// Problem dims
#define MROWS 16384   // B*S
#define DDIM  2048
#define FDIM  128
#define DH    1024
#define SEQ   4096
#define NBATCH 4

// ------------------------- scratch (static, no allocs) -------------------------
__device__ float g_q [(size_t)MROWS * FDIM];
__device__ float g_k2[(size_t)MROWS * FDIM];
__device__ float g_sc[(size_t)MROWS * FDIM];
__device__ float g_H [(size_t)MROWS * DDIM];
__device__ float g_V [(size_t)MROWS * FDIM];
__device__ float g_em[(size_t)MROWS * FDIM];
__device__ float g_xc[(size_t)MROWS * FDIM];
__device__ float g_o1[(size_t)MROWS * DDIM];
__device__ float g_g [(size_t)MROWS * DH];
__device__ float g_o2[(size_t)MROWS * DDIM];

// ------------------------- helpers -------------------------
__device__ __forceinline__ void fma2(float2& d, const float2& a, const float2& b) {
    asm("fma.rn.f32x2 %0, %1, %2, %0;"
        : "+l"(reinterpret_cast<unsigned long long&>(d))
        : "l"(reinterpret_cast<const unsigned long long&>(a)),
          "l"(reinterpret_cast<const unsigned long long&>(b)));
}

__device__ __forceinline__ float sigm(float x) {
    return 1.0f / (1.0f + __expf(-x));
}

// tanh-approximate gelu (JAX default approximate=True)
__device__ __forceinline__ float gelu_f(float x) {
    float z  = 0.7978845608028654f * (x + 0.044715f * x * x * x);
    float az = fabsf(z);
    float e  = __expf(-2.0f * az);
    float t  = (1.0f - e) / (1.0f + e);
    t = copysignf(t, z);
    return 0.5f * x * (1.0f + t);
}

// ------------------------- SGEMM: C[M,N] = A[M,K] @ B[K,N] + bias, epilogue -----
// 128x128 tile, BK=8, 256 threads, 8x8 per thread via fma.rn.f32x2.
// A values stored DUPLICATED in smem so the broadcast operand of f32x2 comes out
// of a single LDS.128 as (a,a,a',a') pairs (no pack MOVs).
// Requires: M%128==0, N%128==0, K%8==0, all pointers 16B aligned.

#define EPI_NONE 0
#define EPI_GELU 1

template <int EPI>
__global__ void __launch_bounds__(256, 2) sgemm_kernel(
    const float* __restrict__ A, const float* __restrict__ Bm,
    const float* __restrict__ bias, float* __restrict__ C,
    int N, int K)
{
    __shared__ float As[2][8][256];  // duplicated along m: As[k][2m]=As[k][2m+1]
    __shared__ float Bs[2][8][128];

    const int  tid = threadIdx.x;
    const long bm  = (long)blockIdx.y * 128;
    const int  bn  = blockIdx.x * 128;

    const int arow = tid >> 1;         // 0..127
    const int acol = (tid & 1) * 4;    // 0 or 4
    const int brow = tid >> 5;         // 0..7
    const int bcol = (tid & 31) * 4;   // 0..124

    const float* Ap = A  + (bm + arow) * (long)K + acol;
    const float* Bp = Bm + (long)brow * N + bn + bcol;

    // stage 0
    {
        float4 a4 = *(const float4*)Ap;
        float4 b4 = *(const float4*)Bp;
        As[0][acol + 0][2 * arow] = a4.x; As[0][acol + 0][2 * arow + 1] = a4.x;
        As[0][acol + 1][2 * arow] = a4.y; As[0][acol + 1][2 * arow + 1] = a4.y;
        As[0][acol + 2][2 * arow] = a4.z; As[0][acol + 2][2 * arow + 1] = a4.z;
        As[0][acol + 3][2 * arow] = a4.w; As[0][acol + 3][2 * arow + 1] = a4.w;
        *(float4*)&Bs[0][brow][bcol] = b4;
    }
    __syncthreads();

    const int tm = (tid >> 4) * 8;     // m offset: 8 consecutive rows
    const int tn = (tid & 15) * 4;     // n offset: cols tn..tn+3 and 64+tn..64+tn+3

    float2 acc[8][4];
#pragma unroll
    for (int i = 0; i < 8; ++i)
#pragma unroll
        for (int j = 0; j < 4; ++j) acc[i][j] = make_float2(0.f, 0.f);

    const int nk = K >> 3;
    for (int kt = 0; kt < nk; ++kt) {
        const int cur = kt & 1;
        float4 na4, nb4;
        const bool more = (kt + 1 < nk);
        if (more) {
            na4 = *(const float4*)(Ap + (kt + 1) * 8);
            nb4 = *(const float4*)(Bp + (long)(kt + 1) * 8 * N);
        }
#pragma unroll
        for (int k = 0; k < 8; ++k) {
            const float4 t0 = *(const float4*)(&As[cur][k][2 * tm + 0]);
            const float4 t1 = *(const float4*)(&As[cur][k][2 * tm + 4]);
            const float4 t2 = *(const float4*)(&As[cur][k][2 * tm + 8]);
            const float4 t3 = *(const float4*)(&As[cur][k][2 * tm + 12]);
            const float4 u0 = *(const float4*)(&Bs[cur][k][tn]);
            const float4 u1 = *(const float4*)(&Bs[cur][k][64 + tn]);
            float2 ad[8], bd[4];
            ad[0] = make_float2(t0.x, t0.y); ad[1] = make_float2(t0.z, t0.w);
            ad[2] = make_float2(t1.x, t1.y); ad[3] = make_float2(t1.z, t1.w);
            ad[4] = make_float2(t2.x, t2.y); ad[5] = make_float2(t2.z, t2.w);
            ad[6] = make_float2(t3.x, t3.y); ad[7] = make_float2(t3.z, t3.w);
            bd[0] = make_float2(u0.x, u0.y); bd[1] = make_float2(u0.z, u0.w);
            bd[2] = make_float2(u1.x, u1.y); bd[3] = make_float2(u1.z, u1.w);
#pragma unroll
            for (int i = 0; i < 8; ++i)
#pragma unroll
                for (int j = 0; j < 4; ++j) fma2(acc[i][j], ad[i], bd[j]);
        }
        if (more) {
            const int nxt = cur ^ 1;
            As[nxt][acol + 0][2 * arow] = na4.x; As[nxt][acol + 0][2 * arow + 1] = na4.x;
            As[nxt][acol + 1][2 * arow] = na4.y; As[nxt][acol + 1][2 * arow + 1] = na4.y;
            As[nxt][acol + 2][2 * arow] = na4.z; As[nxt][acol + 2][2 * arow + 1] = na4.z;
            As[nxt][acol + 3][2 * arow] = na4.w; As[nxt][acol + 3][2 * arow + 1] = na4.w;
            *(float4*)&Bs[nxt][brow][bcol] = nb4;
        }
        __syncthreads();
    }

    // epilogue
    float bb[8];
    *(float4*)&bb[0] = *(const float4*)(bias + bn + tn);
    *(float4*)&bb[4] = *(const float4*)(bias + bn + 64 + tn);
#pragma unroll
    for (int i = 0; i < 8; ++i) {
        float* crow = C + (bm + tm + i) * (long)N + bn;
        float o[8];
        o[0] = acc[i][0].x + bb[0]; o[1] = acc[i][0].y + bb[1];
        o[2] = acc[i][1].x + bb[2]; o[3] = acc[i][1].y + bb[3];
        o[4] = acc[i][2].x + bb[4]; o[5] = acc[i][2].y + bb[5];
        o[6] = acc[i][3].x + bb[6]; o[7] = acc[i][3].y + bb[7];
        if (EPI == EPI_GELU) {
#pragma unroll
            for (int j = 0; j < 8; ++j) o[j] = gelu_f(o[j]);
        }
        *(float4*)(crow + tn)      = make_float4(o[0], o[1], o[2], o[3]);
        *(float4*)(crow + 64 + tn) = make_float4(o[4], o[5], o[6], o[7]);
    }
}

// ------------------------- score = sigmoid(q)*sigmoid(k) -------------------------
__global__ void score_kernel(const float* __restrict__ q, const float* __restrict__ k,
                             float* __restrict__ s, int n)
{
    int i = blockIdx.x * blockDim.x + threadIdx.x;
    if (i < n) s[i] = sigm(q[i]) * sigm(k[i]);
}

// ------------------------- chunked EMA scan over time -------------------------
// ema[0]=s[0]; ema[t]=0.15*s[t]+0.85*ema[t-1]. 0.85^256 ~ 6e-19 -> chunks with
// 256-step warm-up are exact to fp32. Block = 128 threads (one per f), coalesced.
#define EMA_CHUNK 128
#define EMA_WARM  256
__global__ void ema_kernel(const float* __restrict__ sc, float* __restrict__ ema)
{
    const int b  = blockIdx.y;
    const int t0 = blockIdx.x * EMA_CHUNK;
    const int f  = threadIdx.x;
    const float* sb = sc  + ((long)b * SEQ) * FDIM + f;
    float*       eb = ema + ((long)b * SEQ) * FDIM + f;

    int   t = t0 - EMA_WARM;
    float prev;
    if (t <= 0) {
        prev = sb[0];                 // ema[0] = s[0] (exact)
        if (t0 == 0) eb[0] = prev;
        t = 1;
    } else {
        prev = 0.0f;                  // warm-up from zero, 256 steps before t0
    }
    const int tend = t0 + EMA_CHUNK;
    for (; t < tend; ++t) {
        float s = sb[(long)t * FDIM];
        prev = 0.15f * s + 0.85f * prev;
        if (t >= t0) eb[(long)t * FDIM] = prev;
    }
}

// ------------------------- mean over F, clip, multiply V -------------------------
__global__ void normclip_kernel(const float* __restrict__ ema, const float* __restrict__ V,
                                float* __restrict__ xc)
{
    const long row = blockIdx.x;
    const int  f   = threadIdx.x;  // 128
    float e = ema[row * FDIM + f];
    float s = e;
#pragma unroll
    for (int o = 16; o; o >>= 1) s += __shfl_xor_sync(0xffffffffu, s, o);
    __shared__ float ws[4];
    if ((f & 31) == 0) ws[f >> 5] = s;
    __syncthreads();
    float tot = ws[0] + ws[1] + ws[2] + ws[3];
    float denom = fmaxf(tot * (1.0f / 128.0f), 1e-6f);
    float c = e / denom;
    c = fminf(fmaxf(c, -5.0f), 5.0f);
    xc[row * FDIM + f] = c * V[row * FDIM + f];
}

// ------------------------- SwiGLU-style gate -------------------------
__global__ void gate_kernel(const float* __restrict__ o1, float* __restrict__ g, int n)
{
    int i = blockIdx.x * blockDim.x + threadIdx.x;
    if (i < n) {
        long m = (long)(i >> 10);
        int  j = i & 1023;
        float a  = o1[m * DDIM + j];
        float bv = o1[m * DDIM + j + DH];
        g[i] = (a * sigm(a)) * bv;
    }
}

// ------------------------- residual + LayerNorm -------------------------
__global__ void __launch_bounds__(256) ln_kernel(
    const float* __restrict__ o2, const float* __restrict__ x,
    const float* __restrict__ gamma, const float* __restrict__ beta,
    float* __restrict__ y)
{
    __shared__ float ws[8];
    const long row = blockIdx.x;
    const int  tid = threadIdx.x;
    const float* pr = o2 + row * DDIM;
    const float* px = x  + row * DDIM;
    const int c0 = tid * 4;
    const int c1 = 1024 + tid * 4;

    float4 a0 = *(const float4*)(pr + c0), r0 = *(const float4*)(px + c0);
    float4 a1 = *(const float4*)(pr + c1), r1 = *(const float4*)(px + c1);
    float h[8] = { a0.x + r0.x, a0.y + r0.y, a0.z + r0.z, a0.w + r0.w,
                   a1.x + r1.x, a1.y + r1.y, a1.z + r1.z, a1.w + r1.w };

    float s = 0.f;
#pragma unroll
    for (int i = 0; i < 8; ++i) s += h[i];
#pragma unroll
    for (int o = 16; o; o >>= 1) s += __shfl_xor_sync(0xffffffffu, s, o);
    if ((tid & 31) == 0) ws[tid >> 5] = s;
    __syncthreads();
    float tot = 0.f;
#pragma unroll
    for (int i = 0; i < 8; ++i) tot += ws[i];
    const float mu = tot * (1.0f / 2048.0f);
    __syncthreads();

    float sq = 0.f;
#pragma unroll
    for (int i = 0; i < 8; ++i) { float d = h[i] - mu; sq += d * d; }
#pragma unroll
    for (int o = 16; o; o >>= 1) sq += __shfl_xor_sync(0xffffffffu, sq, o);
    if ((tid & 31) == 0) ws[tid >> 5] = sq;
    __syncthreads();
    float tot2 = 0.f;
#pragma unroll
    for (int i = 0; i < 8; ++i) tot2 += ws[i];
    const float inv = rsqrtf(tot2 * (1.0f / 2048.0f) + 1e-5f);

    float4 g0 = *(const float4*)(gamma + c0), g1 = *(const float4*)(gamma + c1);
    float4 b0 = *(const float4*)(beta  + c0), b1 = *(const float4*)(beta  + c1);
    float4 y0, y1;
    y0.x = (h[0] - mu) * inv * g0.x + b0.x;
    y0.y = (h[1] - mu) * inv * g0.y + b0.y;
    y0.z = (h[2] - mu) * inv * g0.z + b0.z;
    y0.w = (h[3] - mu) * inv * g0.w + b0.w;
    y1.x = (h[4] - mu) * inv * g1.x + b1.x;
    y1.y = (h[5] - mu) * inv * g1.y + b1.y;
    y1.z = (h[6] - mu) * inv * g1.z + b1.z;
    y1.w = (h[7] - mu) * inv * g1.w + b1.w;
    *(float4*)(y + row * DDIM + c0) = y0;
    *(float4*)(y + row * DDIM + c1) = y1;
}

// ------------------------- launch -------------------------
extern "C" void kernel_launch(void* const* d_in, const int* in_sizes, int n_in,
                              void* d_out, int out_size)
{
    const float* x      = (const float*)d_in[0];
    const float* Qw     = (const float*)d_in[1];
    const float* Qb     = (const float*)d_in[2];
    const float* Kw     = (const float*)d_in[3];
    const float* Kb     = (const float*)d_in[4];
    const float* low    = (const float*)d_in[5];
    const float* lob    = (const float*)d_in[6];
    const float* lopw   = (const float*)d_in[7];
    const float* lopb   = (const float*)d_in[8];
    const float* projw  = (const float*)d_in[9];
    const float* projb  = (const float*)d_in[10];
    const float* Ow     = (const float*)d_in[11];
    const float* Ob     = (const float*)d_in[12];
    const float* gamma  = (const float*)d_in[13];
    const float* beta   = (const float*)d_in[14];
    float* out = (float*)d_out;

    float *q, *k2, *sc, *H, *V, *em, *xc, *o1, *gg, *o2;
    cudaGetSymbolAddress((void**)&q,  g_q);
    cudaGetSymbolAddress((void**)&k2, g_k2);
    cudaGetSymbolAddress((void**)&sc, g_sc);
    cudaGetSymbolAddress((void**)&H,  g_H);
    cudaGetSymbolAddress((void**)&V,  g_V);
    cudaGetSymbolAddress((void**)&em, g_em);
    cudaGetSymbolAddress((void**)&xc, g_xc);
    cudaGetSymbolAddress((void**)&o1, g_o1);
    cudaGetSymbolAddress((void**)&gg, g_g);
    cudaGetSymbolAddress((void**)&o2, g_o2);

    const dim3 gQK(FDIM / 128, MROWS / 128);
    const dim3 gD (DDIM / 128, MROWS / 128);

    // q = x@Qw + Qb ; k = x@Kw + Kb
    sgemm_kernel<EPI_NONE><<<gQK, 256>>>(x, Qw, Qb, q,  FDIM, DDIM);
    sgemm_kernel<EPI_NONE><<<gQK, 256>>>(x, Kw, Kb, k2, FDIM, DDIM);
    // score = sigmoid(q)*sigmoid(k)
    score_kernel<<<(MROWS * FDIM + 255) / 256, 256>>>(q, k2, sc, MROWS * FDIM);
    // H = gelu(x @ lo_proj_w + lo_proj_b)   (the big one)
    sgemm_kernel<EPI_GELU><<<gD, 256>>>(x, low, lob, H, DDIM, DDIM);
    // V = H @ lo_p_w + lo_p_b
    sgemm_kernel<EPI_NONE><<<gQK, 256>>>(H, lopw, lopb, V, FDIM, DDIM);
    // EMA over time
    ema_kernel<<<dim3(SEQ / EMA_CHUNK, NBATCH), 128>>>(sc, em);
    // x_comb = clip(ema / max(mean_F, eps)) * V
    normclip_kernel<<<MROWS, 128>>>(em, V, xc);
    // out1 = x_comb @ proj_w + proj_b
    sgemm_kernel<EPI_NONE><<<gD, 256>>>(xc, projw, projb, o1, DDIM, FDIM);
    // gated = silu(a) * b
    gate_kernel<<<(MROWS * DH + 255) / 256, 256>>>(o1, gg, MROWS * DH);
    // out2 = gated @ O_w + O_b
    sgemm_kernel<EPI_NONE><<<gD, 256>>>(gg, Ow, Ob, o2, DDIM, DH);
    // residual + LayerNorm
    ln_kernel<<<MROWS, 256>>>(o2, x, gamma, beta, out);
}

// round 4
// speedup vs baseline: 2.4153x; 2.4153x over previous
#include <cuda_runtime.h>
#include <cuda_bf16.h>
#include <cstdint>

// Problem dims
#define MROWS 16384   // B*S
#define DDIM  2048
#define FDIM  128
#define DH    1024
#define SEQ   4096
#define NBATCH 4

// ======================= scratch (static, no allocs) =======================
__device__ __align__(256) float g_qk[(size_t)MROWS * 256];
__device__ __align__(256) float g_sc[(size_t)MROWS * FDIM];
__device__ __align__(256) float g_em[(size_t)MROWS * FDIM];
__device__ __align__(256) float g_V [(size_t)MROWS * FDIM];
__device__ __align__(256) float g_o1[(size_t)MROWS * DDIM];
__device__ __align__(256) float g_o2[(size_t)MROWS * DDIM];
__device__ __align__(256) float g_bqk[256];
// bf16 split activations
__device__ __align__(256) __nv_bfloat16 g_xh [(size_t)MROWS * DDIM];
__device__ __align__(256) __nv_bfloat16 g_xl [(size_t)MROWS * DDIM];
__device__ __align__(256) __nv_bfloat16 g_Hh [(size_t)MROWS * DDIM];
__device__ __align__(256) __nv_bfloat16 g_Hl [(size_t)MROWS * DDIM];
__device__ __align__(256) __nv_bfloat16 g_xch[(size_t)MROWS * FDIM];
__device__ __align__(256) __nv_bfloat16 g_xcl[(size_t)MROWS * FDIM];
__device__ __align__(256) __nv_bfloat16 g_gh [(size_t)MROWS * DH];
__device__ __align__(256) __nv_bfloat16 g_gl [(size_t)MROWS * DH];
// bf16 split transposed weights W^T [N, K] (K contiguous)
__device__ __align__(256) __nv_bfloat16 g_wqk_h[(size_t)256 * DDIM];
__device__ __align__(256) __nv_bfloat16 g_wqk_l[(size_t)256 * DDIM];
__device__ __align__(256) __nv_bfloat16 g_wlo_h[(size_t)DDIM * DDIM];
__device__ __align__(256) __nv_bfloat16 g_wlo_l[(size_t)DDIM * DDIM];
__device__ __align__(256) __nv_bfloat16 g_wlp_h[(size_t)FDIM * DDIM];
__device__ __align__(256) __nv_bfloat16 g_wlp_l[(size_t)FDIM * DDIM];
__device__ __align__(256) __nv_bfloat16 g_wpj_h[(size_t)DDIM * FDIM];
__device__ __align__(256) __nv_bfloat16 g_wpj_l[(size_t)DDIM * FDIM];
__device__ __align__(256) __nv_bfloat16 g_wo_h [(size_t)DDIM * DH];
__device__ __align__(256) __nv_bfloat16 g_wo_l [(size_t)DDIM * DH];

// ======================= helpers =======================
__device__ __forceinline__ uint32_t smem_u32(const void* p) {
    uint32_t a;
    asm("{ .reg .u64 t; cvta.to.shared.u64 t, %1; cvt.u32.u64 %0, t; }" : "=r"(a) : "l"(p));
    return a;
}
__device__ __forceinline__ void ldx4(uint32_t* r, uint32_t addr) {
    asm volatile("ldmatrix.sync.aligned.m8n8.x4.shared.b16 {%0,%1,%2,%3}, [%4];"
        : "=r"(r[0]), "=r"(r[1]), "=r"(r[2]), "=r"(r[3]) : "r"(addr));
}
__device__ __forceinline__ void mma_bf16(float* c, const uint32_t* a, const uint32_t* b) {
    asm volatile("mma.sync.aligned.m16n8k16.row.col.f32.bf16.bf16.f32 "
        "{%0,%1,%2,%3}, {%4,%5,%6,%7}, {%8,%9}, {%0,%1,%2,%3};"
        : "+f"(c[0]), "+f"(c[1]), "+f"(c[2]), "+f"(c[3])
        : "r"(a[0]), "r"(a[1]), "r"(a[2]), "r"(a[3]), "r"(b[0]), "r"(b[1]));
}
__device__ __forceinline__ float sigm(float x) { return 1.0f / (1.0f + __expf(-x)); }
__device__ __forceinline__ float gelu_f(float x) {
    float z  = 0.7978845608028654f * (x + 0.044715f * x * x * x);
    float az = fabsf(z);
    float e  = __expf(-2.0f * az);
    float t  = (1.0f - e) / (1.0f + e);
    t = copysignf(t, z);
    return 0.5f * x * (1.0f + t);
}
__device__ __forceinline__ void split_bf16(float v, __nv_bfloat16& h, __nv_bfloat16& l) {
    h = __float2bfloat16(v);
    l = __float2bfloat16(v - __bfloat162float(h));
}

// ======================= HMMA bf16-split GEMM =======================
// C[M,N] = (Ah+Al)[M,K] @ (Bh+Bl)^T, 3 terms: AhBh + AhBl + AlBh.
// A,B K-major bf16. CTA tile 128x128, BK=32, 256 threads, 8 warps (2x4).
// Smem rows padded to 144B (conflict-free ldmatrix, 16B aligned).
// EPI 0: Cf = acc + bias. EPI 1: gelu(acc+bias) split -> Ch, Cl.
#define TILE_B   18432    // 128 rows * 144B
#define STAGE_B  73728    // 4 tiles
#define HG_SMEM  147456   // 2 stages

template <int EPI>
__global__ void __launch_bounds__(256, 1) hgemm(
    const __nv_bfloat16* __restrict__ Ahp, const __nv_bfloat16* __restrict__ Alp,
    const __nv_bfloat16* __restrict__ Bhp, const __nv_bfloat16* __restrict__ Blp,
    const float* __restrict__ bias,
    float* __restrict__ Cf, __nv_bfloat16* __restrict__ Ch, __nv_bfloat16* __restrict__ Cl,
    int N, int K)
{
    extern __shared__ char smem[];
    const uint32_t sbase = smem_u32(smem);
    const int tid  = threadIdx.x;
    const int wid  = tid >> 5, lane = tid & 31;
    const long bm  = (long)blockIdx.y * 128;
    const long bn  = (long)blockIdx.x * 128;
    const int  wm  = wid >> 2, wn = wid & 3;
    const long kb  = (long)K * 2;   // row stride bytes

    const char* base0 = (const char*)Ahp + bm * kb;
    const char* base1 = (const char*)Alp + bm * kb;
    const char* base2 = (const char*)Bhp + bn * kb;
    const char* base3 = (const char*)Blp + bn * kb;

    // global->smem stage loader: 4 tiles x 128 rows x 64B, 8 chunks/thread
    auto load_stage = [&](int kt, int buf) {
        const uint32_t so = sbase + buf * STAGE_B;
        const long gk = (long)kt * 64;
#pragma unroll
        for (int c = 0; c < 8; ++c) {
            const int t   = c >> 1;
            const int idx = tid + (c & 1) * 256;
            const int row = idx >> 2, col = idx & 3;
            const char* gb = (t == 0) ? base0 : (t == 1) ? base1 : (t == 2) ? base2 : base3;
            const char* gp = gb + (long)row * kb + gk + col * 16;
            const uint32_t sp = so + t * TILE_B + row * 144 + col * 16;
            asm volatile("cp.async.cg.shared.global [%0], [%1], 16;" :: "r"(sp), "l"(gp));
        }
        asm volatile("cp.async.commit_group;" ::: "memory");
    };

    // ldmatrix per-lane address pieces
    const uint32_t g  = lane >> 3, li = lane & 7;
    const uint32_t aRow = wm * 64 + ((g & 1) << 3) + li;   // + mt*16
    const uint32_t aCol = (g >> 1) << 4;                   // + kk*32
    const uint32_t bRow = wn * 32 + ((g >> 1) << 3) + li;  // + pair*16
    const uint32_t bCol = (g & 1) << 4;                    // + kk*32

    float acc[4][4][4];
#pragma unroll
    for (int i = 0; i < 4; ++i)
#pragma unroll
        for (int j = 0; j < 4; ++j)
#pragma unroll
            for (int q = 0; q < 4; ++q) acc[i][j][q] = 0.f;

    load_stage(0, 0);
    const int nk = K >> 5;

    for (int kt = 0; kt < nk; ++kt) {
        const int cur = kt & 1;
        if (kt + 1 < nk) {
            load_stage(kt + 1, cur ^ 1);
            asm volatile("cp.async.wait_group 1;" ::: "memory");
        } else {
            asm volatile("cp.async.wait_group 0;" ::: "memory");
        }
        __syncthreads();

        const uint32_t so = sbase + cur * STAGE_B;
#pragma unroll
        for (int kk = 0; kk < 2; ++kk) {
            uint32_t ah[4][4], al[4][4], bh[4][2], bl[4][2];
#pragma unroll
            for (int mt = 0; mt < 4; ++mt) {
                const uint32_t off = (aRow + mt * 16) * 144 + kk * 32 + aCol;
                ldx4(ah[mt], so + off);
                ldx4(al[mt], so + TILE_B + off);
            }
#pragma unroll
            for (int p = 0; p < 2; ++p) {
                const uint32_t off = (bRow + p * 16) * 144 + kk * 32 + bCol;
                uint32_t r[4];
                ldx4(r, so + 2 * TILE_B + off);
                bh[2*p][0] = r[0]; bh[2*p][1] = r[1];
                bh[2*p+1][0] = r[2]; bh[2*p+1][1] = r[3];
                ldx4(r, so + 3 * TILE_B + off);
                bl[2*p][0] = r[0]; bl[2*p][1] = r[1];
                bl[2*p+1][0] = r[2]; bl[2*p+1][1] = r[3];
            }
#pragma unroll
            for (int mt = 0; mt < 4; ++mt)
#pragma unroll
                for (int nt = 0; nt < 4; ++nt) {
                    mma_bf16(acc[mt][nt], ah[mt], bh[nt]);
                    mma_bf16(acc[mt][nt], ah[mt], bl[nt]);
                    mma_bf16(acc[mt][nt], al[mt], bh[nt]);
                }
        }
        __syncthreads();
    }

    // epilogue: c0,c1 -> (r0, cc..cc+1); c2,c3 -> (r0+8, cc..cc+1)
#pragma unroll
    for (int mt = 0; mt < 4; ++mt) {
        const long r0 = bm + wm * 64 + mt * 16 + (lane >> 2);
#pragma unroll
        for (int nt = 0; nt < 4; ++nt) {
            const long cc = bn + wn * 32 + nt * 8 + (lane & 3) * 2;
            const float2 bv = *(const float2*)(bias + cc);
            float v0 = acc[mt][nt][0] + bv.x, v1 = acc[mt][nt][1] + bv.y;
            float v2 = acc[mt][nt][2] + bv.x, v3 = acc[mt][nt][3] + bv.y;
            if (EPI == 0) {
                *(float2*)(Cf + r0 * N + cc)       = make_float2(v0, v1);
                *(float2*)(Cf + (r0 + 8) * N + cc) = make_float2(v2, v3);
            } else {
                v0 = gelu_f(v0); v1 = gelu_f(v1); v2 = gelu_f(v2); v3 = gelu_f(v3);
                __nv_bfloat16 h0,l0,h1,l1,h2,l2,h3,l3;
                split_bf16(v0,h0,l0); split_bf16(v1,h1,l1);
                split_bf16(v2,h2,l2); split_bf16(v3,h3,l3);
                *(uint32_t*)(Ch + r0 * N + cc) =
                    (uint32_t)__bfloat16_as_ushort(h0) | ((uint32_t)__bfloat16_as_ushort(h1) << 16);
                *(uint32_t*)(Cl + r0 * N + cc) =
                    (uint32_t)__bfloat16_as_ushort(l0) | ((uint32_t)__bfloat16_as_ushort(l1) << 16);
                *(uint32_t*)(Ch + (r0 + 8) * N + cc) =
                    (uint32_t)__bfloat16_as_ushort(h2) | ((uint32_t)__bfloat16_as_ushort(h3) << 16);
                *(uint32_t*)(Cl + (r0 + 8) * N + cc) =
                    (uint32_t)__bfloat16_as_ushort(l2) | ((uint32_t)__bfloat16_as_ushort(l3) << 16);
            }
        }
    }
}

// ======================= weight transpose + bf16 split =======================
__global__ void tsplit_kernel(const float* __restrict__ W,
                              __nv_bfloat16* __restrict__ th, __nv_bfloat16* __restrict__ tl,
                              int K, int N, int rowoff)
{
    __shared__ float t[32][33];
    const int k0 = blockIdx.y * 32, n0 = blockIdx.x * 32;
    const int tx = threadIdx.x, ty = threadIdx.y;
#pragma unroll
    for (int i = ty; i < 32; i += 8)
        t[i][tx] = W[(long)(k0 + i) * N + n0 + tx];
    __syncthreads();
#pragma unroll
    for (int i = ty; i < 32; i += 8) {
        const long n = n0 + i, k = k0 + tx;
        float v = t[tx][i];
        __nv_bfloat16 h, l;
        split_bf16(v, h, l);
        th[(rowoff + n) * (long)K + k] = h;
        tl[(rowoff + n) * (long)K + k] = l;
    }
}

// ======================= activation split (x) =======================
__global__ void split_kernel(const float* __restrict__ x,
                             __nv_bfloat16* __restrict__ h, __nv_bfloat16* __restrict__ l, long n4)
{
    long i = (long)blockIdx.x * blockDim.x + threadIdx.x;
    if (i >= n4) return;
    float4 v = ((const float4*)x)[i];
    __nv_bfloat16 h0,l0,h1,l1,h2,l2,h3,l3;
    split_bf16(v.x, h0, l0); split_bf16(v.y, h1, l1);
    split_bf16(v.z, h2, l2); split_bf16(v.w, h3, l3);
    uint2 hv, lv;
    hv.x = (uint32_t)__bfloat16_as_ushort(h0) | ((uint32_t)__bfloat16_as_ushort(h1) << 16);
    hv.y = (uint32_t)__bfloat16_as_ushort(h2) | ((uint32_t)__bfloat16_as_ushort(h3) << 16);
    lv.x = (uint32_t)__bfloat16_as_ushort(l0) | ((uint32_t)__bfloat16_as_ushort(l1) << 16);
    lv.y = (uint32_t)__bfloat16_as_ushort(l2) | ((uint32_t)__bfloat16_as_ushort(l3) << 16);
    ((uint2*)h)[i] = hv;
    ((uint2*)l)[i] = lv;
}

__global__ void bqk_kernel(const float* __restrict__ Qb, const float* __restrict__ Kb,
                           float* __restrict__ b)
{
    int i = threadIdx.x;
    b[i] = (i < 128) ? Qb[i] : Kb[i - 128];
}

// ======================= score = sigmoid(q)*sigmoid(k) =======================
__global__ void score_kernel(const float* __restrict__ qk, float* __restrict__ s)
{
    long i = (long)blockIdx.x * blockDim.x + threadIdx.x;
    long m = i >> 7;
    int  f = (int)(i & 127);
    s[i] = sigm(qk[m * 256 + f]) * sigm(qk[m * 256 + 128 + f]);
}

// ======================= chunked EMA scan over time =======================
#define EMA_CHUNK 128
#define EMA_WARM  256
__global__ void ema_kernel(const float* __restrict__ sc, float* __restrict__ ema)
{
    const int b  = blockIdx.y;
    const int t0 = blockIdx.x * EMA_CHUNK;
    const int f  = threadIdx.x;
    const float* sb = sc  + ((long)b * SEQ) * FDIM + f;
    float*       eb = ema + ((long)b * SEQ) * FDIM + f;

    int   t = t0 - EMA_WARM;
    float prev;
    if (t <= 0) {
        prev = sb[0];
        if (t0 == 0) eb[0] = prev;
        t = 1;
    } else {
        prev = 0.0f;
    }
    const int tend = t0 + EMA_CHUNK;
    for (; t < tend; ++t) {
        float s = sb[(long)t * FDIM];
        prev = 0.15f * s + 0.85f * prev;
        if (t >= t0) eb[(long)t * FDIM] = prev;
    }
}

// ======================= mean/clip * V -> bf16 hi/lo =======================
__global__ void normclip_kernel(const float* __restrict__ ema, const float* __restrict__ V,
                                __nv_bfloat16* __restrict__ xh, __nv_bfloat16* __restrict__ xl)
{
    const long row = blockIdx.x;
    const int  f   = threadIdx.x;  // 128
    float e = ema[row * FDIM + f];
    float s = e;
#pragma unroll
    for (int o = 16; o; o >>= 1) s += __shfl_xor_sync(0xffffffffu, s, o);
    __shared__ float ws[4];
    if ((f & 31) == 0) ws[f >> 5] = s;
    __syncthreads();
    float tot = ws[0] + ws[1] + ws[2] + ws[3];
    float denom = fmaxf(tot * (1.0f / 128.0f), 1e-6f);
    float c = e / denom;
    c = fminf(fmaxf(c, -5.0f), 5.0f);
    float v = c * V[row * FDIM + f];
    __nv_bfloat16 h, l;
    split_bf16(v, h, l);
    xh[row * FDIM + f] = h;
    xl[row * FDIM + f] = l;
}

// ======================= SwiGLU gate -> bf16 hi/lo =======================
__global__ void gate_kernel(const float* __restrict__ o1,
                            __nv_bfloat16* __restrict__ gh, __nv_bfloat16* __restrict__ gl)
{
    long i = (long)blockIdx.x * blockDim.x + threadIdx.x;
    long m = i >> 10;
    int  j = (int)(i & 1023);
    float a  = o1[m * DDIM + j];
    float bv = o1[m * DDIM + j + DH];
    float v = (a * sigm(a)) * bv;
    __nv_bfloat16 h, l;
    split_bf16(v, h, l);
    gh[i] = h;
    gl[i] = l;
}

// ======================= residual + LayerNorm =======================
__global__ void __launch_bounds__(256) ln_kernel(
    const float* __restrict__ o2, const float* __restrict__ x,
    const float* __restrict__ gamma, const float* __restrict__ beta,
    float* __restrict__ y)
{
    __shared__ float ws[8];
    const long row = blockIdx.x;
    const int  tid = threadIdx.x;
    const float* pr = o2 + row * DDIM;
    const float* px = x  + row * DDIM;
    const int c0 = tid * 4;
    const int c1 = 1024 + tid * 4;

    float4 a0 = *(const float4*)(pr + c0), r0 = *(const float4*)(px + c0);
    float4 a1 = *(const float4*)(pr + c1), r1 = *(const float4*)(px + c1);
    float h[8] = { a0.x + r0.x, a0.y + r0.y, a0.z + r0.z, a0.w + r0.w,
                   a1.x + r1.x, a1.y + r1.y, a1.z + r1.z, a1.w + r1.w };

    float s = 0.f;
#pragma unroll
    for (int i = 0; i < 8; ++i) s += h[i];
#pragma unroll
    for (int o = 16; o; o >>= 1) s += __shfl_xor_sync(0xffffffffu, s, o);
    if ((tid & 31) == 0) ws[tid >> 5] = s;
    __syncthreads();
    float tot = 0.f;
#pragma unroll
    for (int i = 0; i < 8; ++i) tot += ws[i];
    const float mu = tot * (1.0f / 2048.0f);
    __syncthreads();

    float sq = 0.f;
#pragma unroll
    for (int i = 0; i < 8; ++i) { float d = h[i] - mu; sq += d * d; }
#pragma unroll
    for (int o = 16; o; o >>= 1) sq += __shfl_xor_sync(0xffffffffu, sq, o);
    if ((tid & 31) == 0) ws[tid >> 5] = sq;
    __syncthreads();
    float tot2 = 0.f;
#pragma unroll
    for (int i = 0; i < 8; ++i) tot2 += ws[i];
    const float inv = rsqrtf(tot2 * (1.0f / 2048.0f) + 1e-5f);

    float4 g0 = *(const float4*)(gamma + c0), g1 = *(const float4*)(gamma + c1);
    float4 b0 = *(const float4*)(beta  + c0), b1 = *(const float4*)(beta  + c1);
    float4 y0, y1;
    y0.x = (h[0] - mu) * inv * g0.x + b0.x;
    y0.y = (h[1] - mu) * inv * g0.y + b0.y;
    y0.z = (h[2] - mu) * inv * g0.z + b0.z;
    y0.w = (h[3] - mu) * inv * g0.w + b0.w;
    y1.x = (h[4] - mu) * inv * g1.x + b1.x;
    y1.y = (h[5] - mu) * inv * g1.y + b1.y;
    y1.z = (h[6] - mu) * inv * g1.z + b1.z;
    y1.w = (h[7] - mu) * inv * g1.w + b1.w;
    *(float4*)(y + row * DDIM + c0) = y0;
    *(float4*)(y + row * DDIM + c1) = y1;
}

// ======================= launch =======================
extern "C" void kernel_launch(void* const* d_in, const int* in_sizes, int n_in,
                              void* d_out, int out_size)
{
    const float* x      = (const float*)d_in[0];
    const float* Qw     = (const float*)d_in[1];
    const float* Qb     = (const float*)d_in[2];
    const float* Kw     = (const float*)d_in[3];
    const float* Kb     = (const float*)d_in[4];
    const float* low    = (const float*)d_in[5];
    const float* lob    = (const float*)d_in[6];
    const float* lopw   = (const float*)d_in[7];
    const float* lopb   = (const float*)d_in[8];
    const float* projw  = (const float*)d_in[9];
    const float* projb  = (const float*)d_in[10];
    const float* Ow     = (const float*)d_in[11];
    const float* Ob     = (const float*)d_in[12];
    const float* gamma  = (const float*)d_in[13];
    const float* beta   = (const float*)d_in[14];
    float* out = (float*)d_out;

    float *qk, *sc, *em, *V, *o1, *o2, *bqk;
    __nv_bfloat16 *xh, *xl, *Hh, *Hl, *xch, *xcl, *gh, *gl;
    __nv_bfloat16 *wqkh, *wqkl, *wloh, *wlol, *wlph, *wlpl, *wpjh, *wpjl, *woh, *wol;
    cudaGetSymbolAddress((void**)&qk,  g_qk);
    cudaGetSymbolAddress((void**)&sc,  g_sc);
    cudaGetSymbolAddress((void**)&em,  g_em);
    cudaGetSymbolAddress((void**)&V,   g_V);
    cudaGetSymbolAddress((void**)&o1,  g_o1);
    cudaGetSymbolAddress((void**)&o2,  g_o2);
    cudaGetSymbolAddress((void**)&bqk, g_bqk);
    cudaGetSymbolAddress((void**)&xh,  g_xh);
    cudaGetSymbolAddress((void**)&xl,  g_xl);
    cudaGetSymbolAddress((void**)&Hh,  g_Hh);
    cudaGetSymbolAddress((void**)&Hl,  g_Hl);
    cudaGetSymbolAddress((void**)&xch, g_xch);
    cudaGetSymbolAddress((void**)&xcl, g_xcl);
    cudaGetSymbolAddress((void**)&gh,  g_gh);
    cudaGetSymbolAddress((void**)&gl,  g_gl);
    cudaGetSymbolAddress((void**)&wqkh, g_wqk_h);
    cudaGetSymbolAddress((void**)&wqkl, g_wqk_l);
    cudaGetSymbolAddress((void**)&wloh, g_wlo_h);
    cudaGetSymbolAddress((void**)&wlol, g_wlo_l);
    cudaGetSymbolAddress((void**)&wlph, g_wlp_h);
    cudaGetSymbolAddress((void**)&wlpl, g_wlp_l);
    cudaGetSymbolAddress((void**)&wpjh, g_wpj_h);
    cudaGetSymbolAddress((void**)&wpjl, g_wpj_l);
    cudaGetSymbolAddress((void**)&woh,  g_wo_h);
    cudaGetSymbolAddress((void**)&wol,  g_wo_l);

    cudaFuncSetAttribute(hgemm<0>, cudaFuncAttributeMaxDynamicSharedMemorySize, HG_SMEM);
    cudaFuncSetAttribute(hgemm<1>, cudaFuncAttributeMaxDynamicSharedMemorySize, HG_SMEM);

    const dim3 tb32(32, 8);
    // weight transpose + split
    tsplit_kernel<<<dim3(FDIM/32, DDIM/32), tb32>>>(Qw,   wqkh, wqkl, DDIM, FDIM, 0);
    tsplit_kernel<<<dim3(FDIM/32, DDIM/32), tb32>>>(Kw,   wqkh, wqkl, DDIM, FDIM, 128);
    tsplit_kernel<<<dim3(DDIM/32, DDIM/32), tb32>>>(low,  wloh, wlol, DDIM, DDIM, 0);
    tsplit_kernel<<<dim3(FDIM/32, DDIM/32), tb32>>>(lopw, wlph, wlpl, DDIM, FDIM, 0);
    tsplit_kernel<<<dim3(DDIM/32, FDIM/32), tb32>>>(projw,wpjh, wpjl, FDIM, DDIM, 0);
    tsplit_kernel<<<dim3(DDIM/32, DH/32),   tb32>>>(Ow,   woh,  wol,  DH,   DDIM, 0);
    bqk_kernel<<<1, 256>>>(Qb, Kb, bqk);
    // x split
    {
        long n4 = (long)MROWS * DDIM / 4;
        split_kernel<<<(unsigned)((n4 + 255) / 256), 256>>>(x, xh, xl, n4);
    }

    // qk = x @ [Qw|Kw] + [Qb|Kb]
    hgemm<0><<<dim3(2, MROWS/128), 256, HG_SMEM>>>(xh, xl, wqkh, wqkl, bqk, qk, nullptr, nullptr, 256, DDIM);
    score_kernel<<<(MROWS * FDIM) / 256, 256>>>(qk, sc);
    // H = gelu(x @ lo_proj_w + b) -> bf16 hi/lo
    hgemm<1><<<dim3(DDIM/128, MROWS/128), 256, HG_SMEM>>>(xh, xl, wloh, wlol, lob, nullptr, Hh, Hl, DDIM, DDIM);
    // V = H @ lo_p_w + b
    hgemm<0><<<dim3(1, MROWS/128), 256, HG_SMEM>>>(Hh, Hl, wlph, wlpl, lopb, V, nullptr, nullptr, FDIM, DDIM);
    // EMA, norm/clip
    ema_kernel<<<dim3(SEQ / EMA_CHUNK, NBATCH), 128>>>(sc, em);
    normclip_kernel<<<MROWS, 128>>>(em, V, xch, xcl);
    // o1 = xc @ proj_w + b
    hgemm<0><<<dim3(DDIM/128, MROWS/128), 256, HG_SMEM>>>(xch, xcl, wpjh, wpjl, projb, o1, nullptr, nullptr, DDIM, FDIM);
    // gate
    gate_kernel<<<(MROWS * DH) / 256, 256>>>(o1, gh, gl);
    // o2 = g @ O_w + b
    hgemm<0><<<dim3(DDIM/128, MROWS/128), 256, HG_SMEM>>>(gh, gl, woh, wol, Ob, o2, nullptr, nullptr, DDIM, DH);
    // residual + LN
    ln_kernel<<<MROWS, 256>>>(o2, x, gamma, beta, out);
}

// round 5
// speedup vs baseline: 3.5067x; 1.4519x over previous
#include <cuda_runtime.h>
#include <cuda_fp16.h>
#include <cstdint>

// Problem dims
#define MROWS 16384   // B*S
#define DDIM  2048
#define FDIM  128
#define DH    1024
#define SEQ   4096
#define NBATCH 4

// ======================= scratch (static, no allocs) =======================
__device__ __align__(256) float g_qk[(size_t)MROWS * 256];
__device__ __align__(256) float g_sc[(size_t)MROWS * FDIM];
__device__ __align__(256) float g_em[(size_t)MROWS * FDIM];
__device__ __align__(256) float g_V [(size_t)MROWS * FDIM];
__device__ __align__(256) float g_o1[(size_t)MROWS * DDIM];
__device__ __align__(256) float g_o2[(size_t)MROWS * DDIM];
__device__ __align__(256) float g_bqk[256];
// fp16 split activations (hi + lo, exact 2-term split)
__device__ __align__(256) __half g_xh [(size_t)MROWS * DDIM];
__device__ __align__(256) __half g_xl [(size_t)MROWS * DDIM];
__device__ __align__(256) __half g_Hh [(size_t)MROWS * DDIM];
__device__ __align__(256) __half g_Hl [(size_t)MROWS * DDIM];
__device__ __align__(256) __half g_xch[(size_t)MROWS * FDIM];
__device__ __align__(256) __half g_xcl[(size_t)MROWS * FDIM];
__device__ __align__(256) __half g_gh [(size_t)MROWS * DH];
__device__ __align__(256) __half g_gl [(size_t)MROWS * DH];
// fp16 transposed weights W^T [N, K] (K contiguous), single precision term
__device__ __align__(256) __half g_wqk[(size_t)256 * DDIM];
__device__ __align__(256) __half g_wlo[(size_t)DDIM * DDIM];
__device__ __align__(256) __half g_wlp[(size_t)FDIM * DDIM];
__device__ __align__(256) __half g_wpj[(size_t)DDIM * FDIM];
__device__ __align__(256) __half g_wo [(size_t)DDIM * DH];

// ======================= helpers =======================
__device__ __forceinline__ uint32_t smem_u32(const void* p) {
    uint32_t a;
    asm("{ .reg .u64 t; cvta.to.shared.u64 t, %1; cvt.u32.u64 %0, t; }" : "=r"(a) : "l"(p));
    return a;
}
__device__ __forceinline__ void ldx4(uint32_t* r, uint32_t addr) {
    asm volatile("ldmatrix.sync.aligned.m8n8.x4.shared.b16 {%0,%1,%2,%3}, [%4];"
        : "=r"(r[0]), "=r"(r[1]), "=r"(r[2]), "=r"(r[3]) : "r"(addr));
}
__device__ __forceinline__ void mma_fp16(float* c, const uint32_t* a, const uint32_t* b) {
    asm volatile("mma.sync.aligned.m16n8k16.row.col.f32.f16.f16.f32 "
        "{%0,%1,%2,%3}, {%4,%5,%6,%7}, {%8,%9}, {%0,%1,%2,%3};"
        : "+f"(c[0]), "+f"(c[1]), "+f"(c[2]), "+f"(c[3])
        : "r"(a[0]), "r"(a[1]), "r"(a[2]), "r"(a[3]), "r"(b[0]), "r"(b[1]));
}
__device__ __forceinline__ float sigm(float x) { return 1.0f / (1.0f + __expf(-x)); }
__device__ __forceinline__ float gelu_f(float x) {
    float z  = 0.7978845608028654f * (x + 0.044715f * x * x * x);
    float az = fabsf(z);
    float e  = __expf(-2.0f * az);
    float t  = (1.0f - e) / (1.0f + e);
    t = copysignf(t, z);
    return 0.5f * x * (1.0f + t);
}
__device__ __forceinline__ void split_fp16(float v, __half& h, __half& l) {
    h = __float2half_rn(v);
    l = __float2half_rn(v - __half2float(h));
}
__device__ __forceinline__ uint32_t pack2(__half a, __half b) {
    return (uint32_t)__half_as_ushort(a) | ((uint32_t)__half_as_ushort(b) << 16);
}

// ======================= fp16 2-term HMMA GEMM (wide: 128x256, 512 thr) ======
// C[M,N] = (Ah+Al)[M,K] @ Bh^T, 2 terms: AhBh + AlBh. K-major fp16 operands.
// CTA tile 128x256, BK=32, 16 warps (2x8), warp tile 64x32.
// Smem rows padded to 144B (conflict-free ldmatrix, 16B aligned).
// EPI 0: Cf = acc + bias. EPI 1: gelu(acc+bias) split -> Ch, Cl (fp16).
#define ATILE_B  18432    // 128 rows * 144B
#define BTILE_B  36864    // 256 rows * 144B
#define STAGE512 73728
#define SM512    147456

template <int EPI>
__global__ void __launch_bounds__(512, 1) hgemm512(
    const __half* __restrict__ Ahp, const __half* __restrict__ Alp,
    const __half* __restrict__ Bhp,
    const float* __restrict__ bias,
    float* __restrict__ Cf, __half* __restrict__ Ch, __half* __restrict__ Cl,
    int N, int K)
{
    extern __shared__ char smem[];
    const uint32_t sbase = smem_u32(smem);
    const int tid  = threadIdx.x;
    const int wid  = tid >> 5, lane = tid & 31;
    const long bm  = (long)blockIdx.y * 128;
    const long bn  = (long)blockIdx.x * 256;
    const int  wm  = wid >> 3, wn = wid & 7;
    const long kb  = (long)K * 2;   // row stride bytes

    const char* baseAh = (const char*)Ahp + bm * kb;
    const char* baseAl = (const char*)Alp + bm * kb;
    const char* baseB  = (const char*)Bhp + bn * kb;

    const int lrow = tid >> 2, lcol = tid & 3;

    auto load_stage = [&](int kt, int buf) {
        const uint32_t so = sbase + buf * STAGE512;
        const long gk = (long)kt * 64 + lcol * 16;
        const uint32_t sp = so + lrow * 144 + lcol * 16;
        asm volatile("cp.async.cg.shared.global [%0], [%1], 16;"
            :: "r"(sp), "l"(baseAh + (long)lrow * kb + gk));
        asm volatile("cp.async.cg.shared.global [%0], [%1], 16;"
            :: "r"(sp + ATILE_B), "l"(baseAl + (long)lrow * kb + gk));
#pragma unroll
        for (int c = 0; c < 2; ++c) {
            const int row = lrow + c * 128;
            asm volatile("cp.async.cg.shared.global [%0], [%1], 16;"
                :: "r"(so + 2 * ATILE_B + row * 144 + lcol * 16),
                   "l"(baseB + (long)row * kb + gk));
        }
        asm volatile("cp.async.commit_group;" ::: "memory");
    };

    const uint32_t g  = lane >> 3, li = lane & 7;
    const uint32_t aRow = wm * 64 + ((g & 1) << 3) + li;
    const uint32_t aCol = (g >> 1) << 4;
    const uint32_t bRow = wn * 32 + ((g >> 1) << 3) + li;
    const uint32_t bCol = (g & 1) << 4;

    float acc[4][4][4];
#pragma unroll
    for (int i = 0; i < 4; ++i)
#pragma unroll
        for (int j = 0; j < 4; ++j)
#pragma unroll
            for (int q = 0; q < 4; ++q) acc[i][j][q] = 0.f;

    load_stage(0, 0);
    const int nk = K >> 5;

    for (int kt = 0; kt < nk; ++kt) {
        const int cur = kt & 1;
        if (kt + 1 < nk) {
            load_stage(kt + 1, cur ^ 1);
            asm volatile("cp.async.wait_group 1;" ::: "memory");
        } else {
            asm volatile("cp.async.wait_group 0;" ::: "memory");
        }
        __syncthreads();

        const uint32_t so = sbase + cur * STAGE512;
#pragma unroll
        for (int kk = 0; kk < 2; ++kk) {
            uint32_t ah[4][4], al[4][4], bh[4][2];
#pragma unroll
            for (int mt = 0; mt < 4; ++mt) {
                const uint32_t off = (aRow + mt * 16) * 144 + kk * 32 + aCol;
                ldx4(ah[mt], so + off);
                ldx4(al[mt], so + ATILE_B + off);
            }
#pragma unroll
            for (int p = 0; p < 2; ++p) {
                const uint32_t off = (bRow + p * 16) * 144 + kk * 32 + bCol;
                uint32_t r[4];
                ldx4(r, so + 2 * ATILE_B + off);
                bh[2*p][0] = r[0]; bh[2*p][1] = r[1];
                bh[2*p+1][0] = r[2]; bh[2*p+1][1] = r[3];
            }
#pragma unroll
            for (int mt = 0; mt < 4; ++mt)
#pragma unroll
                for (int nt = 0; nt < 4; ++nt) {
                    mma_fp16(acc[mt][nt], ah[mt], bh[nt]);
                    mma_fp16(acc[mt][nt], al[mt], bh[nt]);
                }
        }
        __syncthreads();
    }

#pragma unroll
    for (int mt = 0; mt < 4; ++mt) {
        const long r0 = bm + wm * 64 + mt * 16 + (lane >> 2);
#pragma unroll
        for (int nt = 0; nt < 4; ++nt) {
            const long cc = bn + wn * 32 + nt * 8 + (lane & 3) * 2;
            const float2 bv = *(const float2*)(bias + cc);
            float v0 = acc[mt][nt][0] + bv.x, v1 = acc[mt][nt][1] + bv.y;
            float v2 = acc[mt][nt][2] + bv.x, v3 = acc[mt][nt][3] + bv.y;
            if (EPI == 0) {
                *(float2*)(Cf + r0 * N + cc)       = make_float2(v0, v1);
                *(float2*)(Cf + (r0 + 8) * N + cc) = make_float2(v2, v3);
            } else {
                v0 = gelu_f(v0); v1 = gelu_f(v1); v2 = gelu_f(v2); v3 = gelu_f(v3);
                __half h0,l0,h1,l1,h2,l2,h3,l3;
                split_fp16(v0,h0,l0); split_fp16(v1,h1,l1);
                split_fp16(v2,h2,l2); split_fp16(v3,h3,l3);
                *(uint32_t*)(Ch + r0 * N + cc)       = pack2(h0, h1);
                *(uint32_t*)(Cl + r0 * N + cc)       = pack2(l0, l1);
                *(uint32_t*)(Ch + (r0 + 8) * N + cc) = pack2(h2, h3);
                *(uint32_t*)(Cl + (r0 + 8) * N + cc) = pack2(l2, l3);
            }
        }
    }
}

// ======================= fp16 2-term GEMM (narrow: 128x128, 256 thr) =========
#define STAGE256 55296
#define SM256    110592

__global__ void __launch_bounds__(256, 1) hgemm256(
    const __half* __restrict__ Ahp, const __half* __restrict__ Alp,
    const __half* __restrict__ Bhp,
    const float* __restrict__ bias, float* __restrict__ Cf,
    int N, int K)
{
    extern __shared__ char smem[];
    const uint32_t sbase = smem_u32(smem);
    const int tid  = threadIdx.x;
    const int wid  = tid >> 5, lane = tid & 31;
    const long bm  = (long)blockIdx.y * 128;
    const long bn  = (long)blockIdx.x * 128;
    const int  wm  = wid >> 2, wn = wid & 3;
    const long kb  = (long)K * 2;

    const char* baseAh = (const char*)Ahp + bm * kb;
    const char* baseAl = (const char*)Alp + bm * kb;
    const char* baseB  = (const char*)Bhp + bn * kb;

    auto load_stage = [&](int kt, int buf) {
        const uint32_t so = sbase + buf * STAGE256;
        const long gk = (long)kt * 64;
#pragma unroll
        for (int c = 0; c < 6; ++c) {
            const int t   = c >> 1;
            const int idx = tid + (c & 1) * 256;
            const int row = idx >> 2, col = idx & 3;
            const char* gb = (t == 0) ? baseAh : (t == 1) ? baseAl : baseB;
            const uint32_t sp = so + t * ATILE_B + row * 144 + col * 16;
            asm volatile("cp.async.cg.shared.global [%0], [%1], 16;"
                :: "r"(sp), "l"(gb + (long)row * kb + gk + col * 16));
        }
        asm volatile("cp.async.commit_group;" ::: "memory");
    };

    const uint32_t g  = lane >> 3, li = lane & 7;
    const uint32_t aRow = wm * 64 + ((g & 1) << 3) + li;
    const uint32_t aCol = (g >> 1) << 4;
    const uint32_t bRow = wn * 32 + ((g >> 1) << 3) + li;
    const uint32_t bCol = (g & 1) << 4;

    float acc[4][4][4];
#pragma unroll
    for (int i = 0; i < 4; ++i)
#pragma unroll
        for (int j = 0; j < 4; ++j)
#pragma unroll
            for (int q = 0; q < 4; ++q) acc[i][j][q] = 0.f;

    load_stage(0, 0);
    const int nk = K >> 5;

    for (int kt = 0; kt < nk; ++kt) {
        const int cur = kt & 1;
        if (kt + 1 < nk) {
            load_stage(kt + 1, cur ^ 1);
            asm volatile("cp.async.wait_group 1;" ::: "memory");
        } else {
            asm volatile("cp.async.wait_group 0;" ::: "memory");
        }
        __syncthreads();

        const uint32_t so = sbase + cur * STAGE256;
#pragma unroll
        for (int kk = 0; kk < 2; ++kk) {
            uint32_t ah[4][4], al[4][4], bh[4][2];
#pragma unroll
            for (int mt = 0; mt < 4; ++mt) {
                const uint32_t off = (aRow + mt * 16) * 144 + kk * 32 + aCol;
                ldx4(ah[mt], so + off);
                ldx4(al[mt], so + ATILE_B + off);
            }
#pragma unroll
            for (int p = 0; p < 2; ++p) {
                const uint32_t off = (bRow + p * 16) * 144 + kk * 32 + bCol;
                uint32_t r[4];
                ldx4(r, so + 2 * ATILE_B + off);
                bh[2*p][0] = r[0]; bh[2*p][1] = r[1];
                bh[2*p+1][0] = r[2]; bh[2*p+1][1] = r[3];
            }
#pragma unroll
            for (int mt = 0; mt < 4; ++mt)
#pragma unroll
                for (int nt = 0; nt < 4; ++nt) {
                    mma_fp16(acc[mt][nt], ah[mt], bh[nt]);
                    mma_fp16(acc[mt][nt], al[mt], bh[nt]);
                }
        }
        __syncthreads();
    }

#pragma unroll
    for (int mt = 0; mt < 4; ++mt) {
        const long r0 = bm + wm * 64 + mt * 16 + (lane >> 2);
#pragma unroll
        for (int nt = 0; nt < 4; ++nt) {
            const long cc = bn + wn * 32 + nt * 8 + (lane & 3) * 2;
            const float2 bv = *(const float2*)(bias + cc);
            *(float2*)(Cf + r0 * N + cc) =
                make_float2(acc[mt][nt][0] + bv.x, acc[mt][nt][1] + bv.y);
            *(float2*)(Cf + (r0 + 8) * N + cc) =
                make_float2(acc[mt][nt][2] + bv.x, acc[mt][nt][3] + bv.y);
        }
    }
}

// ======================= weight transpose -> fp16 =======================
__global__ void tsplit_kernel(const float* __restrict__ W,
                              __half* __restrict__ th, int K, int N, int rowoff)
{
    __shared__ float t[32][33];
    const int k0 = blockIdx.y * 32, n0 = blockIdx.x * 32;
    const int tx = threadIdx.x, ty = threadIdx.y;
#pragma unroll
    for (int i = ty; i < 32; i += 8)
        t[i][tx] = W[(long)(k0 + i) * N + n0 + tx];
    __syncthreads();
#pragma unroll
    for (int i = ty; i < 32; i += 8) {
        const long n = n0 + i, k = k0 + tx;
        th[(rowoff + n) * (long)K + k] = __float2half_rn(t[tx][i]);
    }
}

// ======================= activation split (x) =======================
__global__ void split_kernel(const float* __restrict__ x,
                             __half* __restrict__ h, __half* __restrict__ l, long n4)
{
    long i = (long)blockIdx.x * blockDim.x + threadIdx.x;
    if (i >= n4) return;
    float4 v = ((const float4*)x)[i];
    __half h0,l0,h1,l1,h2,l2,h3,l3;
    split_fp16(v.x, h0, l0); split_fp16(v.y, h1, l1);
    split_fp16(v.z, h2, l2); split_fp16(v.w, h3, l3);
    ((uint2*)h)[i] = make_uint2(pack2(h0, h1), pack2(h2, h3));
    ((uint2*)l)[i] = make_uint2(pack2(l0, l1), pack2(l2, l3));
}

__global__ void bqk_kernel(const float* __restrict__ Qb, const float* __restrict__ Kb,
                           float* __restrict__ b)
{
    int i = threadIdx.x;
    b[i] = (i < 128) ? Qb[i] : Kb[i - 128];
}

// ======================= score = sigmoid(q)*sigmoid(k) =======================
__global__ void score_kernel(const float* __restrict__ qk, float* __restrict__ s)
{
    long i = (long)blockIdx.x * blockDim.x + threadIdx.x;
    long m = i >> 7;
    int  f = (int)(i & 127);
    s[i] = sigm(qk[m * 256 + f]) * sigm(qk[m * 256 + 128 + f]);
}

// ======================= chunked EMA scan over time =======================
#define EMA_CHUNK 128
#define EMA_WARM  256
__global__ void ema_kernel(const float* __restrict__ sc, float* __restrict__ ema)
{
    const int b  = blockIdx.y;
    const int t0 = blockIdx.x * EMA_CHUNK;
    const int f  = threadIdx.x;
    const float* sb = sc  + ((long)b * SEQ) * FDIM + f;
    float*       eb = ema + ((long)b * SEQ) * FDIM + f;

    int   t = t0 - EMA_WARM;
    float prev;
    if (t <= 0) {
        prev = sb[0];
        if (t0 == 0) eb[0] = prev;
        t = 1;
    } else {
        prev = 0.0f;
    }
    const int tend = t0 + EMA_CHUNK;
    for (; t < tend; ++t) {
        float s = sb[(long)t * FDIM];
        prev = 0.15f * s + 0.85f * prev;
        if (t >= t0) eb[(long)t * FDIM] = prev;
    }
}

// ======================= mean/clip * V -> fp16 hi/lo =======================
__global__ void normclip_kernel(const float* __restrict__ ema, const float* __restrict__ V,
                                __half* __restrict__ xh, __half* __restrict__ xl)
{
    const long row = blockIdx.x;
    const int  f   = threadIdx.x;  // 128
    float e = ema[row * FDIM + f];
    float s = e;
#pragma unroll
    for (int o = 16; o; o >>= 1) s += __shfl_xor_sync(0xffffffffu, s, o);
    __shared__ float ws[4];
    if ((f & 31) == 0) ws[f >> 5] = s;
    __syncthreads();
    float tot = ws[0] + ws[1] + ws[2] + ws[3];
    float denom = fmaxf(tot * (1.0f / 128.0f), 1e-6f);
    float c = e / denom;
    c = fminf(fmaxf(c, -5.0f), 5.0f);
    float v = c * V[row * FDIM + f];
    __half h, l;
    split_fp16(v, h, l);
    xh[row * FDIM + f] = h;
    xl[row * FDIM + f] = l;
}

// ======================= SwiGLU gate -> fp16 hi/lo =======================
__global__ void gate_kernel(const float* __restrict__ o1,
                            __half* __restrict__ gh, __half* __restrict__ gl)
{
    long i = (long)blockIdx.x * blockDim.x + threadIdx.x;
    long m = i >> 10;
    int  j = (int)(i & 1023);
    float a  = o1[m * DDIM + j];
    float bv = o1[m * DDIM + j + DH];
    float v = (a * sigm(a)) * bv;
    __half h, l;
    split_fp16(v, h, l);
    gh[i] = h;
    gl[i] = l;
}

// ======================= residual + LayerNorm =======================
__global__ void __launch_bounds__(256) ln_kernel(
    const float* __restrict__ o2, const float* __restrict__ x,
    const float* __restrict__ gamma, const float* __restrict__ beta,
    float* __restrict__ y)
{
    __shared__ float ws[8];
    const long row = blockIdx.x;
    const int  tid = threadIdx.x;
    const float* pr = o2 + row * DDIM;
    const float* px = x  + row * DDIM;
    const int c0 = tid * 4;
    const int c1 = 1024 + tid * 4;

    float4 a0 = *(const float4*)(pr + c0), r0 = *(const float4*)(px + c0);
    float4 a1 = *(const float4*)(pr + c1), r1 = *(const float4*)(px + c1);
    float h[8] = { a0.x + r0.x, a0.y + r0.y, a0.z + r0.z, a0.w + r0.w,
                   a1.x + r1.x, a1.y + r1.y, a1.z + r1.z, a1.w + r1.w };

    float s = 0.f;
#pragma unroll
    for (int i = 0; i < 8; ++i) s += h[i];
#pragma unroll
    for (int o = 16; o; o >>= 1) s += __shfl_xor_sync(0xffffffffu, s, o);
    if ((tid & 31) == 0) ws[tid >> 5] = s;
    __syncthreads();
    float tot = 0.f;
#pragma unroll
    for (int i = 0; i < 8; ++i) tot += ws[i];
    const float mu = tot * (1.0f / 2048.0f);
    __syncthreads();

    float sq = 0.f;
#pragma unroll
    for (int i = 0; i < 8; ++i) { float d = h[i] - mu; sq += d * d; }
#pragma unroll
    for (int o = 16; o; o >>= 1) sq += __shfl_xor_sync(0xffffffffu, sq, o);
    if ((tid & 31) == 0) ws[tid >> 5] = sq;
    __syncthreads();
    float tot2 = 0.f;
#pragma unroll
    for (int i = 0; i < 8; ++i) tot2 += ws[i];
    const float inv = rsqrtf(tot2 * (1.0f / 2048.0f) + 1e-5f);

    float4 g0 = *(const float4*)(gamma + c0), g1 = *(const float4*)(gamma + c1);
    float4 b0 = *(const float4*)(beta  + c0), b1 = *(const float4*)(beta  + c1);
    float4 y0, y1;
    y0.x = (h[0] - mu) * inv * g0.x + b0.x;
    y0.y = (h[1] - mu) * inv * g0.y + b0.y;
    y0.z = (h[2] - mu) * inv * g0.z + b0.z;
    y0.w = (h[3] - mu) * inv * g0.w + b0.w;
    y1.x = (h[4] - mu) * inv * g1.x + b1.x;
    y1.y = (h[5] - mu) * inv * g1.y + b1.y;
    y1.z = (h[6] - mu) * inv * g1.z + b1.z;
    y1.w = (h[7] - mu) * inv * g1.w + b1.w;
    *(float4*)(y + row * DDIM + c0) = y0;
    *(float4*)(y + row * DDIM + c1) = y1;
}

// ======================= launch =======================
extern "C" void kernel_launch(void* const* d_in, const int* in_sizes, int n_in,
                              void* d_out, int out_size)
{
    const float* x      = (const float*)d_in[0];
    const float* Qw     = (const float*)d_in[1];
    const float* Qb     = (const float*)d_in[2];
    const float* Kw     = (const float*)d_in[3];
    const float* Kb     = (const float*)d_in[4];
    const float* low    = (const float*)d_in[5];
    const float* lob    = (const float*)d_in[6];
    const float* lopw   = (const float*)d_in[7];
    const float* lopb   = (const float*)d_in[8];
    const float* projw  = (const float*)d_in[9];
    const float* projb  = (const float*)d_in[10];
    const float* Ow     = (const float*)d_in[11];
    const float* Ob     = (const float*)d_in[12];
    const float* gamma  = (const float*)d_in[13];
    const float* beta   = (const float*)d_in[14];
    float* out = (float*)d_out;

    float *qk, *sc, *em, *V, *o1, *o2, *bqk;
    __half *xh, *xl, *Hh, *Hl, *xch, *xcl, *gh, *gl;
    __half *wqk, *wlo, *wlp, *wpj, *wo;
    cudaGetSymbolAddress((void**)&qk,  g_qk);
    cudaGetSymbolAddress((void**)&sc,  g_sc);
    cudaGetSymbolAddress((void**)&em,  g_em);
    cudaGetSymbolAddress((void**)&V,   g_V);
    cudaGetSymbolAddress((void**)&o1,  g_o1);
    cudaGetSymbolAddress((void**)&o2,  g_o2);
    cudaGetSymbolAddress((void**)&bqk, g_bqk);
    cudaGetSymbolAddress((void**)&xh,  g_xh);
    cudaGetSymbolAddress((void**)&xl,  g_xl);
    cudaGetSymbolAddress((void**)&Hh,  g_Hh);
    cudaGetSymbolAddress((void**)&Hl,  g_Hl);
    cudaGetSymbolAddress((void**)&xch, g_xch);
    cudaGetSymbolAddress((void**)&xcl, g_xcl);
    cudaGetSymbolAddress((void**)&gh,  g_gh);
    cudaGetSymbolAddress((void**)&gl,  g_gl);
    cudaGetSymbolAddress((void**)&wqk, g_wqk);
    cudaGetSymbolAddress((void**)&wlo, g_wlo);
    cudaGetSymbolAddress((void**)&wlp, g_wlp);
    cudaGetSymbolAddress((void**)&wpj, g_wpj);
    cudaGetSymbolAddress((void**)&wo,  g_wo);

    cudaFuncSetAttribute(hgemm512<0>, cudaFuncAttributeMaxDynamicSharedMemorySize, SM512);
    cudaFuncSetAttribute(hgemm512<1>, cudaFuncAttributeMaxDynamicSharedMemorySize, SM512);
    cudaFuncSetAttribute(hgemm256,    cudaFuncAttributeMaxDynamicSharedMemorySize, SM256);

    const dim3 tb32(32, 8);
    // weight transpose -> fp16
    tsplit_kernel<<<dim3(FDIM/32, DDIM/32), tb32>>>(Qw,   wqk, DDIM, FDIM, 0);
    tsplit_kernel<<<dim3(FDIM/32, DDIM/32), tb32>>>(Kw,   wqk, DDIM, FDIM, 128);
    tsplit_kernel<<<dim3(DDIM/32, DDIM/32), tb32>>>(low,  wlo, DDIM, DDIM, 0);
    tsplit_kernel<<<dim3(FDIM/32, DDIM/32), tb32>>>(lopw, wlp, DDIM, FDIM, 0);
    tsplit_kernel<<<dim3(DDIM/32, FDIM/32), tb32>>>(projw,wpj, FDIM, DDIM, 0);
    tsplit_kernel<<<dim3(DDIM/32, DH/32),   tb32>>>(Ow,   wo,  DH,   DDIM, 0);
    bqk_kernel<<<1, 256>>>(Qb, Kb, bqk);
    // x split
    {
        long n4 = (long)MROWS * DDIM / 4;
        split_kernel<<<(unsigned)((n4 + 255) / 256), 256>>>(x, xh, xl, n4);
    }

    // qk = x @ [Qw|Kw] + [Qb|Kb]   (N=256 -> one wide tile col)
    hgemm512<0><<<dim3(1, MROWS/128), 512, SM512>>>(xh, xl, wqk, bqk, qk, nullptr, nullptr, 256, DDIM);
    score_kernel<<<(MROWS * FDIM) / 256, 256>>>(qk, sc);
    // H = gelu(x @ lo_proj_w + b) -> fp16 hi/lo
    hgemm512<1><<<dim3(DDIM/256, MROWS/128), 512, SM512>>>(xh, xl, wlo, lob, nullptr, Hh, Hl, DDIM, DDIM);
    // V = H @ lo_p_w + b  (N=128 -> narrow kernel)
    hgemm256<<<dim3(1, MROWS/128), 256, SM256>>>(Hh, Hl, wlp, lopb, V, FDIM, DDIM);
    // EMA, norm/clip
    ema_kernel<<<dim3(SEQ / EMA_CHUNK, NBATCH), 128>>>(sc, em);
    normclip_kernel<<<MROWS, 128>>>(em, V, xch, xcl);
    // o1 = xc @ proj_w + b
    hgemm512<0><<<dim3(DDIM/256, MROWS/128), 512, SM512>>>(xch, xcl, wpj, projb, o1, nullptr, nullptr, DDIM, FDIM);
    // gate
    gate_kernel<<<(MROWS * DH) / 256, 256>>>(o1, gh, gl);
    // o2 = g @ O_w + b
    hgemm512<0><<<dim3(DDIM/256, MROWS/128), 512, SM512>>>(gh, gl, wo, Ob, o2, nullptr, nullptr, DDIM, DH);
    // residual + LN
    ln_kernel<<<MROWS, 256>>>(o2, x, gamma, beta, out);
}

// round 6
// speedup vs baseline: 5.3630x; 1.5293x over previous
#include <cuda_runtime.h>
#include <cuda_fp16.h>
#include <cstdint>

// Problem dims
#define MROWS 16384   // B*S
#define DDIM  2048
#define FDIM  128
#define DH    1024
#define SEQ   4096
#define NBATCH 4

// ======================= scratch (static, no allocs) =======================
__device__ __align__(256) float g_qk[(size_t)MROWS * 256];
__device__ __align__(256) float g_sc[(size_t)MROWS * FDIM];
__device__ __align__(256) float g_em[(size_t)MROWS * FDIM];
__device__ __align__(256) float g_V [(size_t)MROWS * FDIM];
__device__ __align__(256) float g_o1[(size_t)MROWS * DDIM];
__device__ __align__(256) float g_o2[(size_t)MROWS * DDIM];
__device__ __align__(256) float g_bqk[256];
// fp16 activations (single term)
__device__ __align__(256) __half g_xh [(size_t)MROWS * DDIM];
__device__ __align__(256) __half g_Hh [(size_t)MROWS * DDIM];
__device__ __align__(256) __half g_xch[(size_t)MROWS * FDIM];
__device__ __align__(256) __half g_gh [(size_t)MROWS * DH];
// fp16 transposed weights W^T [N, K] (K contiguous)
__device__ __align__(256) __half g_wqk[(size_t)256 * DDIM];
__device__ __align__(256) __half g_wlo[(size_t)DDIM * DDIM];
__device__ __align__(256) __half g_wlp[(size_t)FDIM * DDIM];
__device__ __align__(256) __half g_wpj[(size_t)DDIM * FDIM];
__device__ __align__(256) __half g_wo [(size_t)DDIM * DH];

// ======================= helpers =======================
__device__ __forceinline__ uint32_t smem_u32(const void* p) {
    uint32_t a;
    asm("{ .reg .u64 t; cvta.to.shared.u64 t, %1; cvt.u32.u64 %0, t; }" : "=r"(a) : "l"(p));
    return a;
}
__device__ __forceinline__ void ldx4(uint32_t* r, uint32_t addr) {
    asm volatile("ldmatrix.sync.aligned.m8n8.x4.shared.b16 {%0,%1,%2,%3}, [%4];"
        : "=r"(r[0]), "=r"(r[1]), "=r"(r[2]), "=r"(r[3]) : "r"(addr));
}
__device__ __forceinline__ void mma_fp16(float* c, const uint32_t* a, const uint32_t* b) {
    asm volatile("mma.sync.aligned.m16n8k16.row.col.f32.f16.f16.f32 "
        "{%0,%1,%2,%3}, {%4,%5,%6,%7}, {%8,%9}, {%0,%1,%2,%3};"
        : "+f"(c[0]), "+f"(c[1]), "+f"(c[2]), "+f"(c[3])
        : "r"(a[0]), "r"(a[1]), "r"(a[2]), "r"(a[3]), "r"(b[0]), "r"(b[1]));
}
__device__ __forceinline__ float sigm(float x) { return 1.0f / (1.0f + __expf(-x)); }
__device__ __forceinline__ float gelu_f(float x) {
    float z  = 0.7978845608028654f * (x + 0.044715f * x * x * x);
    float az = fabsf(z);
    float e  = __expf(-2.0f * az);
    float t  = (1.0f - e) / (1.0f + e);
    t = copysignf(t, z);
    return 0.5f * x * (1.0f + t);
}
__device__ __forceinline__ uint32_t pack2(__half a, __half b) {
    return (uint32_t)__half_as_ushort(a) | ((uint32_t)__half_as_ushort(b) << 16);
}

// row stride in smem: 64B data (BK=32 fp16) + 16B pad -> conflict-free ldmatrix
#define RSTR 80

// ======================= fp16 HMMA GEMM (wide: 128x256, 512 thr) =============
// C[M,N] = A[M,K](fp16) @ B^T[N,K](fp16). BK=32, 4-stage cp.async pipeline,
// 16 warps (2x8), warp tile 64x32.
// EPI 0: Cf = acc + bias (f32). EPI 1: gelu(acc+bias) -> Ch (fp16).
#define A512   10240          // 128*RSTR
#define B512   20480          // 256*RSTR
#define STG512 30720
#define SM512  122880         // 4 stages

template <int EPI>
__global__ void __launch_bounds__(512, 1) hgemm512(
    const __half* __restrict__ Ap, const __half* __restrict__ Bp,
    const float* __restrict__ bias,
    float* __restrict__ Cf, __half* __restrict__ Ch,
    int N, int K)
{
    extern __shared__ char smem[];
    const uint32_t sbase = smem_u32(smem);
    const int tid  = threadIdx.x;
    const int wid  = tid >> 5, lane = tid & 31;
    const long bm  = (long)blockIdx.y * 128;
    const long bn  = (long)blockIdx.x * 256;
    const int  wm  = wid >> 3, wn = wid & 7;
    const long kb  = (long)K * 2;

    const char* baseA = (const char*)Ap + bm * kb;
    const char* baseB = (const char*)Bp + bn * kb;
    const int lrow = tid >> 2, lcol = tid & 3;

    auto load_stage = [&](int kt, int buf) {
        const uint32_t so = sbase + buf * STG512;
        const long gk = (long)kt * 64 + lcol * 16;
        asm volatile("cp.async.cg.shared.global [%0], [%1], 16;"
            :: "r"(so + lrow * RSTR + lcol * 16), "l"(baseA + (long)lrow * kb + gk));
#pragma unroll
        for (int c = 0; c < 2; ++c) {
            const int row = lrow + c * 128;
            asm volatile("cp.async.cg.shared.global [%0], [%1], 16;"
                :: "r"(so + A512 + row * RSTR + lcol * 16), "l"(baseB + (long)row * kb + gk));
        }
        asm volatile("cp.async.commit_group;" ::: "memory");
    };

    const uint32_t g  = lane >> 3, li = lane & 7;
    const uint32_t aRow = wm * 64 + ((g & 1) << 3) + li;
    const uint32_t aCol = (g >> 1) << 4;
    const uint32_t bRow = wn * 32 + ((g >> 1) << 3) + li;
    const uint32_t bCol = (g & 1) << 4;

    float acc[4][4][4];
#pragma unroll
    for (int i = 0; i < 4; ++i)
#pragma unroll
        for (int j = 0; j < 4; ++j)
#pragma unroll
            for (int q = 0; q < 4; ++q) acc[i][j][q] = 0.f;

    const int nk = K >> 5;
    load_stage(0, 0);
    if (nk > 1) load_stage(1, 1);
    if (nk > 2) load_stage(2, 2);

    for (int kt = 0; kt < nk; ++kt) {
        // wait until stage kt is resident
        if (kt <= nk - 3)      asm volatile("cp.async.wait_group 2;" ::: "memory");
        else if (kt == nk - 2) asm volatile("cp.async.wait_group 1;" ::: "memory");
        else                   asm volatile("cp.async.wait_group 0;" ::: "memory");
        __syncthreads();
        if (kt + 3 < nk) load_stage(kt + 3, (kt + 3) & 3);

        const uint32_t so = sbase + (kt & 3) * STG512;
#pragma unroll
        for (int kk = 0; kk < 2; ++kk) {
            uint32_t ah[4][4], bh[4][2];
#pragma unroll
            for (int mt = 0; mt < 4; ++mt)
                ldx4(ah[mt], so + (aRow + mt * 16) * RSTR + kk * 32 + aCol);
#pragma unroll
            for (int p = 0; p < 2; ++p) {
                uint32_t r[4];
                ldx4(r, so + A512 + (bRow + p * 16) * RSTR + kk * 32 + bCol);
                bh[2*p][0] = r[0]; bh[2*p][1] = r[1];
                bh[2*p+1][0] = r[2]; bh[2*p+1][1] = r[3];
            }
#pragma unroll
            for (int mt = 0; mt < 4; ++mt)
#pragma unroll
                for (int nt = 0; nt < 4; ++nt)
                    mma_fp16(acc[mt][nt], ah[mt], bh[nt]);
        }
    }

#pragma unroll
    for (int mt = 0; mt < 4; ++mt) {
        const long r0 = bm + wm * 64 + mt * 16 + (lane >> 2);
#pragma unroll
        for (int nt = 0; nt < 4; ++nt) {
            const long cc = bn + wn * 32 + nt * 8 + (lane & 3) * 2;
            const float2 bv = *(const float2*)(bias + cc);
            float v0 = acc[mt][nt][0] + bv.x, v1 = acc[mt][nt][1] + bv.y;
            float v2 = acc[mt][nt][2] + bv.x, v3 = acc[mt][nt][3] + bv.y;
            if (EPI == 0) {
                *(float2*)(Cf + r0 * N + cc)       = make_float2(v0, v1);
                *(float2*)(Cf + (r0 + 8) * N + cc) = make_float2(v2, v3);
            } else {
                *(uint32_t*)(Ch + r0 * N + cc) =
                    pack2(__float2half_rn(gelu_f(v0)), __float2half_rn(gelu_f(v1)));
                *(uint32_t*)(Ch + (r0 + 8) * N + cc) =
                    pack2(__float2half_rn(gelu_f(v2)), __float2half_rn(gelu_f(v3)));
            }
        }
    }
}

// ======================= fp16 GEMM (narrow: 128x128, 256 thr) ================
#define STG256 20480
#define SM256  81920

__global__ void __launch_bounds__(256, 2) hgemm256(
    const __half* __restrict__ Ap, const __half* __restrict__ Bp,
    const float* __restrict__ bias, float* __restrict__ Cf,
    int N, int K)
{
    extern __shared__ char smem[];
    const uint32_t sbase = smem_u32(smem);
    const int tid  = threadIdx.x;
    const int wid  = tid >> 5, lane = tid & 31;
    const long bm  = (long)blockIdx.y * 128;
    const long bn  = (long)blockIdx.x * 128;
    const int  wm  = wid >> 2, wn = wid & 3;
    const long kb  = (long)K * 2;

    const char* baseA = (const char*)Ap + bm * kb;
    const char* baseB = (const char*)Bp + bn * kb;
    const int lrow0 = tid >> 2, lcol = tid & 3;

    auto load_stage = [&](int kt, int buf) {
        const uint32_t so = sbase + buf * STG256;
        const long gk = (long)kt * 64 + lcol * 16;
#pragma unroll
        for (int c = 0; c < 2; ++c) {
            const int row = lrow0 + c * 64;
            asm volatile("cp.async.cg.shared.global [%0], [%1], 16;"
                :: "r"(so + row * RSTR + lcol * 16), "l"(baseA + (long)row * kb + gk));
            asm volatile("cp.async.cg.shared.global [%0], [%1], 16;"
                :: "r"(so + A512 + row * RSTR + lcol * 16), "l"(baseB + (long)row * kb + gk));
        }
        asm volatile("cp.async.commit_group;" ::: "memory");
    };

    const uint32_t g  = lane >> 3, li = lane & 7;
    const uint32_t aRow = wm * 64 + ((g & 1) << 3) + li;
    const uint32_t aCol = (g >> 1) << 4;
    const uint32_t bRow = wn * 32 + ((g >> 1) << 3) + li;
    const uint32_t bCol = (g & 1) << 4;

    float acc[4][4][4];
#pragma unroll
    for (int i = 0; i < 4; ++i)
#pragma unroll
        for (int j = 0; j < 4; ++j)
#pragma unroll
            for (int q = 0; q < 4; ++q) acc[i][j][q] = 0.f;

    const int nk = K >> 5;
    load_stage(0, 0);
    if (nk > 1) load_stage(1, 1);
    if (nk > 2) load_stage(2, 2);

    for (int kt = 0; kt < nk; ++kt) {
        if (kt <= nk - 3)      asm volatile("cp.async.wait_group 2;" ::: "memory");
        else if (kt == nk - 2) asm volatile("cp.async.wait_group 1;" ::: "memory");
        else                   asm volatile("cp.async.wait_group 0;" ::: "memory");
        __syncthreads();
        if (kt + 3 < nk) load_stage(kt + 3, (kt + 3) & 3);

        const uint32_t so = sbase + (kt & 3) * STG256;
#pragma unroll
        for (int kk = 0; kk < 2; ++kk) {
            uint32_t ah[4][4], bh[4][2];
#pragma unroll
            for (int mt = 0; mt < 4; ++mt)
                ldx4(ah[mt], so + (aRow + mt * 16) * RSTR + kk * 32 + aCol);
#pragma unroll
            for (int p = 0; p < 2; ++p) {
                uint32_t r[4];
                ldx4(r, so + A512 + (bRow + p * 16) * RSTR + kk * 32 + bCol);
                bh[2*p][0] = r[0]; bh[2*p][1] = r[1];
                bh[2*p+1][0] = r[2]; bh[2*p+1][1] = r[3];
            }
#pragma unroll
            for (int mt = 0; mt < 4; ++mt)
#pragma unroll
                for (int nt = 0; nt < 4; ++nt)
                    mma_fp16(acc[mt][nt], ah[mt], bh[nt]);
        }
    }

#pragma unroll
    for (int mt = 0; mt < 4; ++mt) {
        const long r0 = bm + wm * 64 + mt * 16 + (lane >> 2);
#pragma unroll
        for (int nt = 0; nt < 4; ++nt) {
            const long cc = bn + wn * 32 + nt * 8 + (lane & 3) * 2;
            const float2 bv = *(const float2*)(bias + cc);
            *(float2*)(Cf + r0 * N + cc) =
                make_float2(acc[mt][nt][0] + bv.x, acc[mt][nt][1] + bv.y);
            *(float2*)(Cf + (r0 + 8) * N + cc) =
                make_float2(acc[mt][nt][2] + bv.x, acc[mt][nt][3] + bv.y);
        }
    }
}

// ======================= weight transpose -> fp16 =======================
__global__ void tsplit_kernel(const float* __restrict__ W,
                              __half* __restrict__ th, int K, int N, int rowoff)
{
    __shared__ float t[32][33];
    const int k0 = blockIdx.y * 32, n0 = blockIdx.x * 32;
    const int tx = threadIdx.x, ty = threadIdx.y;
#pragma unroll
    for (int i = ty; i < 32; i += 8)
        t[i][tx] = W[(long)(k0 + i) * N + n0 + tx];
    __syncthreads();
#pragma unroll
    for (int i = ty; i < 32; i += 8) {
        const long n = n0 + i, k = k0 + tx;
        th[(rowoff + n) * (long)K + k] = __float2half_rn(t[tx][i]);
    }
}

// ======================= x -> fp16 =======================
__global__ void cvt_kernel(const float* __restrict__ x, __half* __restrict__ h, long n4)
{
    long i = (long)blockIdx.x * blockDim.x + threadIdx.x;
    if (i >= n4) return;
    float4 v = ((const float4*)x)[i];
    ((uint2*)h)[i] = make_uint2(
        pack2(__float2half_rn(v.x), __float2half_rn(v.y)),
        pack2(__float2half_rn(v.z), __float2half_rn(v.w)));
}

__global__ void bqk_kernel(const float* __restrict__ Qb, const float* __restrict__ Kb,
                           float* __restrict__ b)
{
    int i = threadIdx.x;
    b[i] = (i < 128) ? Qb[i] : Kb[i - 128];
}

// ======================= score = sigmoid(q)*sigmoid(k) =======================
// qk layout: [M, 256] with q in cols 0..127, k in cols 128..255
__global__ void score_kernel(const float* __restrict__ qk, float* __restrict__ s)
{
    long i = (long)blockIdx.x * blockDim.x + threadIdx.x;
    long m = i >> 7;
    int  f = (int)(i & 127);
    s[i] = sigm(qk[m * 256 + f]) * sigm(qk[m * 256 + 128 + f]);
}

// ======================= chunked EMA scan over time =======================
#define EMA_CHUNK 128
#define EMA_WARM  256
__global__ void ema_kernel(const float* __restrict__ sc, float* __restrict__ ema)
{
    const int b  = blockIdx.y;
    const int t0 = blockIdx.x * EMA_CHUNK;
    const int f  = threadIdx.x;
    const float* sb = sc  + ((long)b * SEQ) * FDIM + f;
    float*       eb = ema + ((long)b * SEQ) * FDIM + f;

    int   t = t0 - EMA_WARM;
    float prev;
    if (t <= 0) {
        prev = sb[0];
        if (t0 == 0) eb[0] = prev;
        t = 1;
    } else {
        prev = 0.0f;
    }
    const int tend = t0 + EMA_CHUNK;
    for (; t < tend; ++t) {
        float s = sb[(long)t * FDIM];
        prev = 0.15f * s + 0.85f * prev;
        if (t >= t0) eb[(long)t * FDIM] = prev;
    }
}

// ======================= mean/clip * V -> fp16 =======================
__global__ void normclip_kernel(const float* __restrict__ ema, const float* __restrict__ V,
                                __half* __restrict__ xh)
{
    const long row = blockIdx.x;
    const int  f   = threadIdx.x;  // 128
    float e = ema[row * FDIM + f];
    float s = e;
#pragma unroll
    for (int o = 16; o; o >>= 1) s += __shfl_xor_sync(0xffffffffu, s, o);
    __shared__ float ws[4];
    if ((f & 31) == 0) ws[f >> 5] = s;
    __syncthreads();
    float tot = ws[0] + ws[1] + ws[2] + ws[3];
    float denom = fmaxf(tot * (1.0f / 128.0f), 1e-6f);
    float c = e / denom;
    c = fminf(fmaxf(c, -5.0f), 5.0f);
    xh[row * FDIM + f] = __float2half_rn(c * V[row * FDIM + f]);
}

// ======================= SwiGLU gate -> fp16 =======================
__global__ void gate_kernel(const float* __restrict__ o1, __half* __restrict__ gh)
{
    long i = (long)blockIdx.x * blockDim.x + threadIdx.x;
    long m = i >> 10;
    int  j = (int)(i & 1023);
    float a  = o1[m * DDIM + j];
    float bv = o1[m * DDIM + j + DH];
    gh[i] = __float2half_rn((a * sigm(a)) * bv);
}

// ======================= residual + LayerNorm =======================
__global__ void __launch_bounds__(256) ln_kernel(
    const float* __restrict__ o2, const float* __restrict__ x,
    const float* __restrict__ gamma, const float* __restrict__ beta,
    float* __restrict__ y)
{
    __shared__ float ws[8];
    const long row = blockIdx.x;
    const int  tid = threadIdx.x;
    const float* pr = o2 + row * DDIM;
    const float* px = x  + row * DDIM;
    const int c0 = tid * 4;
    const int c1 = 1024 + tid * 4;

    float4 a0 = *(const float4*)(pr + c0), r0 = *(const float4*)(px + c0);
    float4 a1 = *(const float4*)(pr + c1), r1 = *(const float4*)(px + c1);
    float h[8] = { a0.x + r0.x, a0.y + r0.y, a0.z + r0.z, a0.w + r0.w,
                   a1.x + r1.x, a1.y + r1.y, a1.z + r1.z, a1.w + r1.w };

    float s = 0.f;
#pragma unroll
    for (int i = 0; i < 8; ++i) s += h[i];
#pragma unroll
    for (int o = 16; o; o >>= 1) s += __shfl_xor_sync(0xffffffffu, s, o);
    if ((tid & 31) == 0) ws[tid >> 5] = s;
    __syncthreads();
    float tot = 0.f;
#pragma unroll
    for (int i = 0; i < 8; ++i) tot += ws[i];
    const float mu = tot * (1.0f / 2048.0f);
    __syncthreads();

    float sq = 0.f;
#pragma unroll
    for (int i = 0; i < 8; ++i) { float d = h[i] - mu; sq += d * d; }
#pragma unroll
    for (int o = 16; o; o >>= 1) sq += __shfl_xor_sync(0xffffffffu, sq, o);
    if ((tid & 31) == 0) ws[tid >> 5] = sq;
    __syncthreads();
    float tot2 = 0.f;
#pragma unroll
    for (int i = 0; i < 8; ++i) tot2 += ws[i];
    const float inv = rsqrtf(tot2 * (1.0f / 2048.0f) + 1e-5f);

    float4 g0 = *(const float4*)(gamma + c0), g1 = *(const float4*)(gamma + c1);
    float4 b0 = *(const float4*)(beta  + c0), b1 = *(const float4*)(beta  + c1);
    float4 y0, y1;
    y0.x = (h[0] - mu) * inv * g0.x + b0.x;
    y0.y = (h[1] - mu) * inv * g0.y + b0.y;
    y0.z = (h[2] - mu) * inv * g0.z + b0.z;
    y0.w = (h[3] - mu) * inv * g0.w + b0.w;
    y1.x = (h[4] - mu) * inv * g1.x + b1.x;
    y1.y = (h[5] - mu) * inv * g1.y + b1.y;
    y1.z = (h[6] - mu) * inv * g1.z + b1.z;
    y1.w = (h[7] - mu) * inv * g1.w + b1.w;
    *(float4*)(y + row * DDIM + c0) = y0;
    *(float4*)(y + row * DDIM + c1) = y1;
}

// ======================= launch =======================
extern "C" void kernel_launch(void* const* d_in, const int* in_sizes, int n_in,
                              void* d_out, int out_size)
{
    const float* x      = (const float*)d_in[0];
    const float* Qw     = (const float*)d_in[1];
    const float* Qb     = (const float*)d_in[2];
    const float* Kw     = (const float*)d_in[3];
    const float* Kb     = (const float*)d_in[4];
    const float* low    = (const float*)d_in[5];
    const float* lob    = (const float*)d_in[6];
    const float* lopw   = (const float*)d_in[7];
    const float* lopb   = (const float*)d_in[8];
    const float* projw  = (const float*)d_in[9];
    const float* projb  = (const float*)d_in[10];
    const float* Ow     = (const float*)d_in[11];
    const float* Ob     = (const float*)d_in[12];
    const float* gamma  = (const float*)d_in[13];
    const float* beta   = (const float*)d_in[14];
    float* out = (float*)d_out;

    float *qk, *sc, *em, *V, *o1, *o2, *bqk;
    __half *xh, *Hh, *xch, *gh;
    __half *wqk, *wlo, *wlp, *wpj, *wo;
    cudaGetSymbolAddress((void**)&qk,  g_qk);
    cudaGetSymbolAddress((void**)&sc,  g_sc);
    cudaGetSymbolAddress((void**)&em,  g_em);
    cudaGetSymbolAddress((void**)&V,   g_V);
    cudaGetSymbolAddress((void**)&o1,  g_o1);
    cudaGetSymbolAddress((void**)&o2,  g_o2);
    cudaGetSymbolAddress((void**)&bqk, g_bqk);
    cudaGetSymbolAddress((void**)&xh,  g_xh);
    cudaGetSymbolAddress((void**)&Hh,  g_Hh);
    cudaGetSymbolAddress((void**)&xch, g_xch);
    cudaGetSymbolAddress((void**)&gh,  g_gh);
    cudaGetSymbolAddress((void**)&wqk, g_wqk);
    cudaGetSymbolAddress((void**)&wlo, g_wlo);
    cudaGetSymbolAddress((void**)&wlp, g_wlp);
    cudaGetSymbolAddress((void**)&wpj, g_wpj);
    cudaGetSymbolAddress((void**)&wo,  g_wo);

    cudaFuncSetAttribute(hgemm512<0>, cudaFuncAttributeMaxDynamicSharedMemorySize, SM512);
    cudaFuncSetAttribute(hgemm512<1>, cudaFuncAttributeMaxDynamicSharedMemorySize, SM512);
    cudaFuncSetAttribute(hgemm256,    cudaFuncAttributeMaxDynamicSharedMemorySize, SM256);

    const dim3 tb32(32, 8);
    // weight transpose -> fp16
    tsplit_kernel<<<dim3(FDIM/32, DDIM/32), tb32>>>(Qw,   wqk, DDIM, FDIM, 0);
    tsplit_kernel<<<dim3(FDIM/32, DDIM/32), tb32>>>(Kw,   wqk, DDIM, FDIM, 128);
    tsplit_kernel<<<dim3(DDIM/32, DDIM/32), tb32>>>(low,  wlo, DDIM, DDIM, 0);
    tsplit_kernel<<<dim3(FDIM/32, DDIM/32), tb32>>>(lopw, wlp, DDIM, FDIM, 0);
    tsplit_kernel<<<dim3(DDIM/32, FDIM/32), tb32>>>(projw,wpj, FDIM, DDIM, 0);
    tsplit_kernel<<<dim3(DDIM/32, DH/32),   tb32>>>(Ow,   wo,  DH,   DDIM, 0);
    bqk_kernel<<<1, 256>>>(Qb, Kb, bqk);
    // x -> fp16
    {
        long n4 = (long)MROWS * DDIM / 4;
        cvt_kernel<<<(unsigned)((n4 + 255) / 256), 256>>>(x, xh, n4);
    }

    // qk = x @ [Qw|Kw] + [Qb|Kb]  (narrow kernel, 256 CTAs)
    hgemm256<<<dim3(2, MROWS/128), 256, SM256>>>(xh, wqk, bqk, qk, 256, DDIM);
    score_kernel<<<(MROWS * FDIM) / 256, 256>>>(qk, sc);
    // H = gelu(x @ lo_proj_w + b) -> fp16
    hgemm512<1><<<dim3(DDIM/256, MROWS/128), 512, SM512>>>(xh, wlo, lob, nullptr, Hh, DDIM, DDIM);
    // V = H @ lo_p_w + b
    hgemm256<<<dim3(1, MROWS/128), 256, SM256>>>(Hh, wlp, lopb, V, FDIM, DDIM);
    // EMA, norm/clip
    ema_kernel<<<dim3(SEQ / EMA_CHUNK, NBATCH), 128>>>(sc, em);
    normclip_kernel<<<MROWS, 128>>>(em, V, xch);
    // o1 = xc @ proj_w + b
    hgemm512<0><<<dim3(DDIM/256, MROWS/128), 512, SM512>>>(xch, wpj, projb, o1, nullptr, DDIM, FDIM);
    // gate
    gate_kernel<<<(MROWS * DH) / 256, 256>>>(o1, gh);
    // o2 = g @ O_w + b
    hgemm512<0><<<dim3(DDIM/256, MROWS/128), 512, SM512>>>(gh, wo, Ob, o2, nullptr, DDIM, DH);
    // residual + LN
    ln_kernel<<<MROWS, 256>>>(o2, x, gamma, beta, out);
}